// round 12
// baseline (speedup 1.0000x reference)
#include <cuda_runtime.h>
#include <cuda_bf16.h>

// Problem constants (fixed by the reference)
#define B 8
#define N 2048
#define M 8192
#define C 64
#define NSEG 2048

#define CAP 32        // bucket capacity; multiplicity ~ Poisson(4), P(>=32) ~ 1e-26
#define NGROUPS 4     // independent batch-group pipelines
#define BPG (B / NGROUPS)   // 2 batches per group

// Scratch. Invariant: every g_bucket word is a valid row id in [0, M)
// (zero-init at load; only valid m ever stored; never zeroed afterwards).
__device__ int g_cnt_i[B * NSEG];          // 64 KB
__device__ int g_bucket[B * NSEG * CAP];   // 2 MB

// ---------------------------------------------------------------------------
// Bucket for one 2-batch group. One thread per (b_local, m).
// Side job: L2-prefetch of own source row (overlaps the atomic's latency).
// ---------------------------------------------------------------------------
__global__ void bucket_kernel(const int* __restrict__ index_source,
                              const float* __restrict__ array_source,
                              int b0) {
    int T = blockIdx.x * blockDim.x + threadIdx.x;   // [0, BPG*M)
    if (T >= BPG * M) return;

    {   // L2-only touch of this row's two 128B lines (results unused).
        const char* row = reinterpret_cast<const char*>(array_source)
                        + ((size_t)b0 * M + T) * 256;
        unsigned d0, d1;
        asm volatile("ld.global.cg.b32 %0, [%1];"     : "=r"(d0) : "l"(row) : "memory");
        asm volatile("ld.global.cg.b32 %0, [%1+128];" : "=r"(d1) : "l"(row) : "memory");
    }

    int b   = b0 + (T >> 13);                        // M = 8192 = 2^13
    int seg = __ldg(&index_source[b0 * M + T]);
    int si  = (b << 11) + seg;                       // NSEG = 2048 = 2^11
    int pos = atomicAdd(&g_cnt_i[si], 1);
    if (pos < CAP) {
        g_bucket[(si << 5) + pos] = T & (M - 1);     // m within batch
    }
}

// ---------------------------------------------------------------------------
// Gather for one 2-batch group — round-7 inner shape (measured best).
// ---------------------------------------------------------------------------
__global__ void gather_kernel(const int* __restrict__ index_target,
                              const float* __restrict__ array_source,
                              float* __restrict__ out,
                              int b0) {
    int t = blockIdx.x * blockDim.x + threadIdx.x;   // [0, BPG*N*16)
    if (t >= BPG * N * (C / 4)) return;
    int c4  = t & 15;
    int bnl = t >> 4;                                // local (b,n) in group
    int b   = b0 + (bnl >> 11);                      // N = 2048 = 2^11
    int seg = __ldg(&index_target[b0 * N + bnl]);
    int si  = (b << 11) + seg;

    int cnt = __ldcg(&g_cnt_i[si]);
    int lim = min(cnt, CAP);

    const float4* src4 = reinterpret_cast<const float4*>(array_source);
    int src_base = (b << 13) * 16;                   // b*M rows * 16 quads/row
    const int4* bk = reinterpret_cast<const int4*>(&g_bucket[si << 5]);

    float4 acc = make_float4(0.f, 0.f, 0.f, 0.f);
#pragma unroll 1
    for (int i0 = 0; i0 < lim; i0 += 4) {
        int4 ms = __ldcg(&bk[i0 >> 2]);              // 4 row ids, lane-broadcast
        if (i0 + 0 < lim) {
            float4 s = __ldg(&src4[src_base + ms.x * 16 + c4]);
            acc.x += s.x; acc.y += s.y; acc.z += s.z; acc.w += s.w;
        }
        if (i0 + 1 < lim) {
            float4 s = __ldg(&src4[src_base + ms.y * 16 + c4]);
            acc.x += s.x; acc.y += s.y; acc.z += s.z; acc.w += s.w;
        }
        if (i0 + 2 < lim) {
            float4 s = __ldg(&src4[src_base + ms.z * 16 + c4]);
            acc.x += s.x; acc.y += s.y; acc.z += s.z; acc.w += s.w;
        }
        if (i0 + 3 < lim) {
            float4 s = __ldg(&src4[src_base + ms.w * 16 + c4]);
            acc.x += s.x; acc.y += s.y; acc.z += s.z; acc.w += s.w;
        }
    }

    float inv = 1.0f / (1e-10f + (float)cnt);
    acc.x *= inv; acc.y *= inv; acc.z *= inv; acc.w *= inv;
    reinterpret_cast<float4*>(out)[(size_t)b0 * N * 16 + t] = acc;
}

// ---------------------------------------------------------------------------
// Host: 4 independent pipelines (memset slice -> bucket -> gather), forked
// from the capture stream with events and joined at the end. Streams/events
// are host-side resources created once; the captured work is identical on
// every call.
// ---------------------------------------------------------------------------
extern "C" void kernel_launch(void* const* d_in, const int* in_sizes, int n_in,
                              void* d_out, int out_size) {
    const int*   index_target = (const int*)d_in[0];   // [B, N, 1]
    const int*   index_source = (const int*)d_in[1];   // [B, M, 1]
    const float* array_source = (const float*)d_in[2]; // [B, M, C]
    float*       out          = (float*)d_out;         // [B, N, C]

    (void)in_sizes; (void)n_in; (void)out_size;

    struct Resources {
        cudaStream_t s[NGROUPS - 1];
        cudaEvent_t  fork;
        cudaEvent_t  join[NGROUPS - 1];
        Resources() {
            for (int i = 0; i < NGROUPS - 1; i++) {
                cudaStreamCreateWithFlags(&s[i], cudaStreamNonBlocking);
                cudaEventCreateWithFlags(&join[i], cudaEventDisableTiming);
            }
            cudaEventCreateWithFlags(&fork, cudaEventDisableTiming);
        }
    };
    static Resources R;   // created on first (uncaptured correctness) call

    void* cnt_ptr = nullptr;
    cudaGetSymbolAddress(&cnt_ptr, g_cnt_i);

    // Fork: side streams join the capture via the event.
    cudaEventRecord(R.fork, 0);
    for (int i = 0; i < NGROUPS - 1; i++) {
        cudaStreamWaitEvent(R.s[i], R.fork, 0);
    }

    const int bucket_total = BPG * M;              // 16,384 threads
    const int gather_total = BPG * N * (C / 4);    // 65,536 threads
    const size_t cnt_slice = (size_t)BPG * NSEG * sizeof(int);  // 16 KB

    for (int g = 0; g < NGROUPS; g++) {
        cudaStream_t st = (g == 0) ? (cudaStream_t)0 : R.s[g - 1];
        int b0 = g * BPG;
        cudaMemsetAsync((char*)cnt_ptr + (size_t)b0 * NSEG * sizeof(int),
                        0, cnt_slice, st);
        bucket_kernel<<<(bucket_total + 255) / 256, 256, 0, st>>>(
            index_source, array_source, b0);
        gather_kernel<<<(gather_total + 255) / 256, 256, 0, st>>>(
            index_target, array_source, out, b0);
    }

    // Join: capture stream waits for the side pipelines.
    for (int i = 0; i < NGROUPS - 1; i++) {
        cudaEventRecord(R.join[i], R.s[i]);
        cudaStreamWaitEvent((cudaStream_t)0, R.join[i], 0);
    }
}

// round 13
// speedup vs baseline: 1.2100x; 1.2100x over previous
#include <cuda_runtime.h>
#include <cuda_bf16.h>

// Problem constants (fixed by the reference)
#define B 8
#define N 2048
#define M 8192
#define C 64
#define NSEG 2048

#define CAP 32   // bucket capacity; multiplicity ~ Poisson(4), P(>=32) ~ 1e-26

// Scratch. Invariant: every g_bucket word is a valid row id in [0, M)
// (zero-init at load; only valid m ever stored; never zeroed afterwards).
__device__ int g_cnt_i[B * NSEG];          // 64 KB
__device__ int g_bucket[B * NSEG * CAP];   // 2 MB

// ---------------------------------------------------------------------------
// Kernel 1: bucket the source rows. One thread per (b, m).
// PDL: prologue (index load + L2 source prefetch) is independent of the
// memset; grid-dependency sync only before the atomic that needs zeroed cnt.
// ---------------------------------------------------------------------------
__global__ void bucket_kernel(const int* __restrict__ index_source,
                              const float* __restrict__ array_source) {
    int T = blockIdx.x * blockDim.x + threadIdx.x;   // [0, B*M)
    if (T >= B * M) {
        cudaGridDependencySynchronize();
        return;
    }

    // Independent prologue: own seg id + L2-only touch of own source row.
    int seg = __ldg(&index_source[T]);
    {
        const char* row = reinterpret_cast<const char*>(array_source) + (size_t)T * 256;
        unsigned d0, d1;
        asm volatile("ld.global.cg.b32 %0, [%1];"     : "=r"(d0) : "l"(row) : "memory");
        asm volatile("ld.global.cg.b32 %0, [%1+128];" : "=r"(d1) : "l"(row) : "memory");
    }

    cudaGridDependencySynchronize();                 // wait: cnt memset done

    int b   = T >> 13;                               // M = 8192 = 2^13
    int si  = (b << 11) + seg;                       // NSEG = 2048 = 2^11
    int pos = atomicAdd(&g_cnt_i[si], 1);
    if (pos < CAP) {
        g_bucket[(si << 5) + pos] = T & (M - 1);
    }
}

// ---------------------------------------------------------------------------
// Kernel 2: gather — round-7/11 inner shape (measured best).
// PDL: prologue (target seg load + index math) is independent of the bucket
// kernel; sync only before reading cnt/bucket.
// ---------------------------------------------------------------------------
__global__ void gather_kernel(const int* __restrict__ index_target,
                              const float* __restrict__ array_source,
                              float* __restrict__ out) {
    int t = blockIdx.x * blockDim.x + threadIdx.x;   // [0, B*N*16)
    if (t >= B * N * (C / 4)) {
        cudaGridDependencySynchronize();
        return;
    }
    int c4  = t & 15;
    int bn  = t >> 4;
    int b   = bn >> 11;                              // N = 2048 = 2^11
    int seg = __ldg(&index_target[bn]);              // independent of buckets
    int si  = (b << 11) + seg;

    cudaGridDependencySynchronize();                 // wait: buckets complete

    int cnt = __ldcg(&g_cnt_i[si]);
    int lim = min(cnt, CAP);

    const float4* src4 = reinterpret_cast<const float4*>(array_source);
    int src_base = (b << 13) * 16;                   // b*M rows * 16 quads/row
    const int4* bk = reinterpret_cast<const int4*>(&g_bucket[si << 5]);

    float4 acc = make_float4(0.f, 0.f, 0.f, 0.f);
#pragma unroll 1
    for (int i0 = 0; i0 < lim; i0 += 4) {
        int4 ms = __ldcg(&bk[i0 >> 2]);              // 4 row ids, lane-broadcast
        if (i0 + 0 < lim) {
            float4 s = __ldg(&src4[src_base + ms.x * 16 + c4]);
            acc.x += s.x; acc.y += s.y; acc.z += s.z; acc.w += s.w;
        }
        if (i0 + 1 < lim) {
            float4 s = __ldg(&src4[src_base + ms.y * 16 + c4]);
            acc.x += s.x; acc.y += s.y; acc.z += s.z; acc.w += s.w;
        }
        if (i0 + 2 < lim) {
            float4 s = __ldg(&src4[src_base + ms.z * 16 + c4]);
            acc.x += s.x; acc.y += s.y; acc.z += s.z; acc.w += s.w;
        }
        if (i0 + 3 < lim) {
            float4 s = __ldg(&src4[src_base + ms.w * 16 + c4]);
            acc.x += s.x; acc.y += s.y; acc.z += s.z; acc.w += s.w;
        }
    }

    float inv = 1.0f / (1e-10f + (float)cnt);
    acc.x *= inv; acc.y *= inv; acc.z *= inv; acc.w *= inv;
    reinterpret_cast<float4*>(out)[t] = acc;
}

// ---------------------------------------------------------------------------
extern "C" void kernel_launch(void* const* d_in, const int* in_sizes, int n_in,
                              void* d_out, int out_size) {
    const int*   index_target = (const int*)d_in[0];   // [B, N, 1]
    const int*   index_source = (const int*)d_in[1];   // [B, M, 1]
    const float* array_source = (const float*)d_in[2]; // [B, M, C]
    float*       out          = (float*)d_out;         // [B, N, C]

    (void)in_sizes; (void)n_in; (void)out_size;

    void* cnt_ptr = nullptr;
    cudaGetSymbolAddress(&cnt_ptr, g_cnt_i);
    cudaMemsetAsync(cnt_ptr, 0, (size_t)B * NSEG * sizeof(int), 0);

    cudaLaunchAttribute pdl[1];
    pdl[0].id = cudaLaunchAttributeProgrammaticStreamSerialization;
    pdl[0].val.programmaticStreamSerializationAllowed = 1;

    {   // bucket: 65,536 threads, PDL vs the memset
        cudaLaunchConfig_t cfg = {};
        cfg.gridDim  = dim3((B * M + 255) / 256);
        cfg.blockDim = dim3(256);
        cfg.stream   = 0;
        cfg.attrs    = pdl;
        cfg.numAttrs = 1;
        cudaLaunchKernelEx(&cfg, bucket_kernel, index_source, array_source);
    }
    {   // gather: 262,144 threads, PDL vs bucket
        cudaLaunchConfig_t cfg = {};
        cfg.gridDim  = dim3((B * N * (C / 4) + 255) / 256);
        cfg.blockDim = dim3(256);
        cfg.stream   = 0;
        cfg.attrs    = pdl;
        cfg.numAttrs = 1;
        cudaLaunchKernelEx(&cfg, gather_kernel, index_target, array_source, out);
    }
}